// round 14
// baseline (speedup 1.0000x reference)
#include <cuda_runtime.h>
#include <cstdint>
#include <cstring>

// EquivariantLayerNorm: out = (covar + EPS*I)^{-1/2} @ (x - mean) * weight
// covar = xc @ xc^T / D + EPS*diag(1,2,3),  x: (N, 3, 256) fp32.
//
// R14 = R13 (warp-per-sample, register-resident via __ldcs, 5-level
// butterfly, closed-form A^{-1/2}, streaming stores, barrier-free) with
// the bulk FMA work converted to packed f32x2 (FFMA2): reduction dots and
// the whole epilogue transform run on (x,y)/(z,w) register pairs,
// halving the dominant instruction count (fma pipe was 35%, issue 51%).

__device__ __forceinline__ float2 fma2(float2 a, float2 b, float2 c) {
    unsigned long long ua, ub, uc, ud;
    memcpy(&ua, &a, 8); memcpy(&ub, &b, 8); memcpy(&uc, &c, 8);
    asm("fma.rn.f32x2 %0, %1, %2, %3;" : "=l"(ud) : "l"(ua), "l"(ub), "l"(uc));
    float2 d; memcpy(&d, &ud, 8);
    return d;
}
__device__ __forceinline__ float2 mul2(float2 a, float2 b) {
    unsigned long long ua, ub, ud;
    memcpy(&ua, &a, 8); memcpy(&ub, &b, 8);
    asm("mul.rn.f32x2 %0, %1, %2;" : "=l"(ud) : "l"(ua), "l"(ub));
    float2 d; memcpy(&d, &ud, 8);
    return d;
}
__device__ __forceinline__ float2 add2(float2 a, float2 b) {
    unsigned long long ua, ub, ud;
    memcpy(&ua, &a, 8); memcpy(&ub, &b, 8);
    asm("add.rn.f32x2 %0, %1, %2;" : "=l"(ud) : "l"(ua), "l"(ub));
    float2 d; memcpy(&d, &ud, 8);
    return d;
}
__device__ __forceinline__ float2 lo2(float4 v) { return make_float2(v.x, v.y); }
__device__ __forceinline__ float2 hi2(float4 v) { return make_float2(v.z, v.w); }

__global__ void __launch_bounds__(64, 12) eqln_kernel(
    const float* __restrict__ in,
    const float* __restrict__ weight,
    float* __restrict__ out,
    int nSamples)
{
    const int warp = threadIdx.x >> 5;   // 0..1
    const int lane = threadIdx.x & 31;

    long sample = (long)blockIdx.x * 2 + warp;
    const bool valid = (sample < (long)nSamples);
    long ls = valid ? sample : (long)nSamples - 1;   // clamp for safe load

    // ---- front-batched register loads: 6 independent LDG.128 per lane ----
    const float4* __restrict__ xin = (const float4*)(in + ls * 768);
    float4 x[6];
    x[0] = __ldcs(&xin[       lane]);
    x[1] = __ldcs(&xin[ 32 +  lane]);
    x[2] = __ldcs(&xin[ 64 +  lane]);
    x[3] = __ldcs(&xin[ 96 +  lane]);
    x[4] = __ldcs(&xin[128 +  lane]);
    x[5] = __ldcs(&xin[160 +  lane]);

    // ---- 9-quantity reduction with packed f32x2 accumulators ----
    const float2 z2 = make_float2(0.0f, 0.0f);
    float s[9];
    {
        // row sums
        float2 r0 = add2(add2(lo2(x[0]), hi2(x[0])), add2(lo2(x[1]), hi2(x[1])));
        float2 r1 = add2(add2(lo2(x[2]), hi2(x[2])), add2(lo2(x[3]), hi2(x[3])));
        float2 r2 = add2(add2(lo2(x[4]), hi2(x[4])), add2(lo2(x[5]), hi2(x[5])));
        s[0] = r0.x + r0.y;
        s[1] = r1.x + r1.y;
        s[2] = r2.x + r2.y;
        // second moments: 4 packed fma per dot (was 8 scalar)
        float2 p;
        p = fma2(lo2(x[0]), lo2(x[0]), fma2(hi2(x[0]), hi2(x[0]),
            fma2(lo2(x[1]), lo2(x[1]), fma2(hi2(x[1]), hi2(x[1]), z2))));
        s[3] = p.x + p.y;
        p = fma2(lo2(x[0]), lo2(x[2]), fma2(hi2(x[0]), hi2(x[2]),
            fma2(lo2(x[1]), lo2(x[3]), fma2(hi2(x[1]), hi2(x[3]), z2))));
        s[4] = p.x + p.y;
        p = fma2(lo2(x[0]), lo2(x[4]), fma2(hi2(x[0]), hi2(x[4]),
            fma2(lo2(x[1]), lo2(x[5]), fma2(hi2(x[1]), hi2(x[5]), z2))));
        s[5] = p.x + p.y;
        p = fma2(lo2(x[2]), lo2(x[2]), fma2(hi2(x[2]), hi2(x[2]),
            fma2(lo2(x[3]), lo2(x[3]), fma2(hi2(x[3]), hi2(x[3]), z2))));
        s[6] = p.x + p.y;
        p = fma2(lo2(x[2]), lo2(x[4]), fma2(hi2(x[2]), hi2(x[4]),
            fma2(lo2(x[3]), lo2(x[5]), fma2(hi2(x[3]), hi2(x[5]), z2))));
        s[7] = p.x + p.y;
        p = fma2(lo2(x[4]), lo2(x[4]), fma2(hi2(x[4]), hi2(x[4]),
            fma2(lo2(x[5]), lo2(x[5]), fma2(hi2(x[5]), hi2(x[5]), z2))));
        s[8] = p.x + p.y;
    }

    // 5-level butterfly: every lane ends with the full sums
    #pragma unroll
    for (int q = 0; q < 9; q++) {
        #pragma unroll
        for (int o = 16; o > 0; o >>= 1)
            s[q] += __shfl_xor_sync(0xffffffffu, s[q], o);
    }

    // ---- closed-form A^{-1/2} (redundant across the 32 lanes) ----
    const float invD = 1.0f / 256.0f;
    const float m0 = s[0] * invD, m1 = s[1] * invD, m2 = s[2] * invD;

    // A = covar + EPS*diag(1,2,3) + EPS*I   (the +EPS*I from 1/sqrt(s+eps))
    const float a00 = fmaf(s[3], invD, -m0 * m0) + 2.0e-3f;
    const float a01 = fmaf(s[4], invD, -m0 * m1);
    const float a02 = fmaf(s[5], invD, -m0 * m2);
    const float a11 = fmaf(s[6], invD, -m1 * m1) + 3.0e-3f;
    const float a12 = fmaf(s[7], invD, -m1 * m2);
    const float a22 = fmaf(s[8], invD, -m2 * m2) + 4.0e-3f;

    // eigenvalues (trigonometric method); A >= 2e-3 I so all roots positive
    const float qm  = (a00 + a11 + a22) * (1.0f / 3.0f);
    const float d0 = a00 - qm, d1 = a11 - qm, d2 = a22 - qm;
    const float off2 = a01*a01 + a02*a02 + a12*a12;
    float p2 = (d0*d0 + d1*d1 + d2*d2) * (1.0f / 6.0f) + off2 * (1.0f / 3.0f);
    p2 = fmaxf(p2, 1.0e-24f);
    const float detB = d0 * (d1*d2 - a12*a12)
                     - a01 * (a01*d2 - a12*a02)
                     + a02 * (a01*a12 - d1*a02);
    const float ip  = rsqrtf(p2);            // 1/p
    float r = 0.5f * detB * (ip * ip * ip);
    r = fminf(fmaxf(r, -1.0f), 1.0f);
    const float phi = acosf(r) * (1.0f / 3.0f);
    const float twop = 2.0f * p2 * ip;       // 2p
    const float l1 = qm + twop * __cosf(phi);                 // largest
    const float l3 = qm + twop * __cosf(phi + 2.0943951f);    // smallest
    const float l2 = 3.0f * qm - l1 - l3;

    // cancellation-free divided differences of f(x)=1/sqrt(x)
    const float u = sqrtf(l1), v = sqrtf(l2), w = sqrtf(l3);
    const float uv = u + v, vw = v + w, uw = u + w;
    const float rden = 1.0f / ((u * v * w) * uv * vw * uw);
    const float c2 = (u + v + w) * rden;
    const float c1 = -(w * vw * uw) * rden;
    const float c0 = (v * w) * (vw * uv * uw) * rden;   // = 1/u

    // S = c0*I + c1*(A-l1 I) + c2*(A-l1 I)(A-l2 I)
    const float e0 = a00 - l1, e1 = a11 - l1, e2 = a22 - l1;
    const float g0 = a00 - l2, g1 = a11 - l2, g2 = a22 - l2;
    const float P00 = e0*g0 + a01*a01 + a02*a02;
    const float P01 = a01*(e0 + g1) + a02*a12;
    const float P02 = a02*(e0 + g2) + a01*a12;
    const float P11 = a01*a01 + e1*g1 + a12*a12;
    const float P12 = a12*(e1 + g2) + a01*a02;
    const float P22 = a02*a02 + a12*a12 + e2*g2;

    const float S00 = fmaf(c2, P00, fmaf(c1, e0, c0));
    const float S01 = fmaf(c2, P01, c1 * a01);
    const float S02 = fmaf(c2, P02, c1 * a02);
    const float S11 = fmaf(c2, P11, fmaf(c1, e1, c0));
    const float S12 = fmaf(c2, P12, c1 * a12);
    const float S22 = fmaf(c2, P22, fmaf(c1, e2, c0));

    // bias b = -S*m folds the mean subtraction into the transform
    const float bb0 = -(S00*m0 + S01*m1 + S02*m2);
    const float bb1 = -(S01*m0 + S11*m1 + S12*m2);
    const float bb2 = -(S02*m0 + S12*m1 + S22*m2);

    // packed broadcast copies for the epilogue
    const float2 S00p = make_float2(S00, S00), S01p = make_float2(S01, S01);
    const float2 S02p = make_float2(S02, S02), S11p = make_float2(S11, S11);
    const float2 S12p = make_float2(S12, S12), S22p = make_float2(S22, S22);
    const float2 bb0p = make_float2(bb0, bb0), bb1p = make_float2(bb1, bb1);
    const float2 bb2p = make_float2(bb2, bb2);

    // ---- epilogue: packed transform from registers, streaming stores ----
    if (valid) {
        const float4* __restrict__ w4p = (const float4*)weight;
        float4* __restrict__ xout = (float4*)(out + sample * 768);

        #pragma unroll
        for (int c = 0; c < 2; c++) {
            float4 a = x[c], b = x[2 + c], d = x[4 + c];
            float4 wq = __ldg(&w4p[c * 32 + lane]);
            const float2 wlo = lo2(wq), whi = hi2(wq);
            const float2 alo = lo2(a), ahi = hi2(a);
            const float2 blo = lo2(b), bhi = hi2(b);
            const float2 dlo = lo2(d), dhi = hi2(d);

            float2 olo, ohi;
            float4 o;

            olo = mul2(fma2(S00p, alo, fma2(S01p, blo, fma2(S02p, dlo, bb0p))), wlo);
            ohi = mul2(fma2(S00p, ahi, fma2(S01p, bhi, fma2(S02p, dhi, bb0p))), whi);
            o.x = olo.x; o.y = olo.y; o.z = ohi.x; o.w = ohi.y;
            __stcs(&xout[       c * 32 + lane], o);

            olo = mul2(fma2(S01p, alo, fma2(S11p, blo, fma2(S12p, dlo, bb1p))), wlo);
            ohi = mul2(fma2(S01p, ahi, fma2(S11p, bhi, fma2(S12p, dhi, bb1p))), whi);
            o.x = olo.x; o.y = olo.y; o.z = ohi.x; o.w = ohi.y;
            __stcs(&xout[ 64 +  c * 32 + lane], o);

            olo = mul2(fma2(S02p, alo, fma2(S12p, blo, fma2(S22p, dlo, bb2p))), wlo);
            ohi = mul2(fma2(S02p, ahi, fma2(S12p, bhi, fma2(S22p, dhi, bb2p))), whi);
            o.x = olo.x; o.y = olo.y; o.z = ohi.x; o.w = ohi.y;
            __stcs(&xout[128 +  c * 32 + lane], o);
        }
    }
}

extern "C" void kernel_launch(void* const* d_in, const int* in_sizes, int n_in,
                              void* d_out, int out_size)
{
    const float* in = (const float*)d_in[0];
    const float* w  = (const float*)d_in[1];
    float* out      = (float*)d_out;

    int nSamples = in_sizes[0] / 768;        // N*3*256 elements -> N samples
    int grid = (nSamples + 1) / 2;           // 2 samples per 64-thread block
    eqln_kernel<<<grid, 64>>>(in, w, out, nSamples);
}

// round 15
// speedup vs baseline: 1.0045x; 1.0045x over previous
#include <cuda_runtime.h>
#include <cstdint>

// EquivariantLayerNorm: out = (covar + EPS*I)^{-1/2} @ (x - mean) * weight
// covar = xc @ xc^T / D + EPS*diag(1,2,3),  x: (N, 3, 256) fp32.
//
// R15 = R13 (champion: warp-per-sample, register-resident via __ldcs,
// 5-level butterfly, closed-form A^{-1/2}, streaming stores, barrier-free)
// at the finest CTA granularity: 32-thread blocks, one sample per block,
// 32 CTAs/SM (RF exactly full at 64 regs). Minimal drain window, finest
// scheduler grain. All math identical to R13.

__device__ __forceinline__ float sum4(float4 a) {
    return (a.x + a.y) + (a.z + a.w);
}
__device__ __forceinline__ float dot4(float4 a, float4 b, float acc) {
    acc = fmaf(a.x, b.x, acc);
    acc = fmaf(a.y, b.y, acc);
    acc = fmaf(a.z, b.z, acc);
    acc = fmaf(a.w, b.w, acc);
    return acc;
}

__global__ void __launch_bounds__(32, 24) eqln_kernel(
    const float* __restrict__ in,
    const float* __restrict__ weight,
    float* __restrict__ out,
    int nSamples)
{
    const int lane = threadIdx.x & 31;

    long sample = (long)blockIdx.x;
    const bool valid = (sample < (long)nSamples);
    long ls = valid ? sample : (long)nSamples - 1;   // clamp for safe load

    // ---- front-batched register loads: 6 independent LDG.128 per lane ----
    const float4* __restrict__ xin = (const float4*)(in + ls * 768);
    float4 x[6];
    x[0] = __ldcs(&xin[       lane]);
    x[1] = __ldcs(&xin[ 32 +  lane]);
    x[2] = __ldcs(&xin[ 64 +  lane]);
    x[3] = __ldcs(&xin[ 96 +  lane]);
    x[4] = __ldcs(&xin[128 +  lane]);
    x[5] = __ldcs(&xin[160 +  lane]);

    // ---- 9-quantity reduction (row sums + raw second moments) ----
    float s[9];
    s[0] = sum4(x[0]) + sum4(x[1]);
    s[1] = sum4(x[2]) + sum4(x[3]);
    s[2] = sum4(x[4]) + sum4(x[5]);
    s[3] = dot4(x[1], x[1], dot4(x[0], x[0], 0.0f));
    s[4] = dot4(x[1], x[3], dot4(x[0], x[2], 0.0f));
    s[5] = dot4(x[1], x[5], dot4(x[0], x[4], 0.0f));
    s[6] = dot4(x[3], x[3], dot4(x[2], x[2], 0.0f));
    s[7] = dot4(x[3], x[5], dot4(x[2], x[4], 0.0f));
    s[8] = dot4(x[5], x[5], dot4(x[4], x[4], 0.0f));

    // 5-level butterfly: every lane ends with the full sums
    #pragma unroll
    for (int q = 0; q < 9; q++) {
        #pragma unroll
        for (int o = 16; o > 0; o >>= 1)
            s[q] += __shfl_xor_sync(0xffffffffu, s[q], o);
    }

    // ---- closed-form A^{-1/2} (redundant across the 32 lanes) ----
    const float invD = 1.0f / 256.0f;
    const float m0 = s[0] * invD, m1 = s[1] * invD, m2 = s[2] * invD;

    // A = covar + EPS*diag(1,2,3) + EPS*I   (the +EPS*I from 1/sqrt(s+eps))
    const float a00 = fmaf(s[3], invD, -m0 * m0) + 2.0e-3f;
    const float a01 = fmaf(s[4], invD, -m0 * m1);
    const float a02 = fmaf(s[5], invD, -m0 * m2);
    const float a11 = fmaf(s[6], invD, -m1 * m1) + 3.0e-3f;
    const float a12 = fmaf(s[7], invD, -m1 * m2);
    const float a22 = fmaf(s[8], invD, -m2 * m2) + 4.0e-3f;

    // eigenvalues (trigonometric method); A >= 2e-3 I so all roots positive
    const float qm  = (a00 + a11 + a22) * (1.0f / 3.0f);
    const float d0 = a00 - qm, d1 = a11 - qm, d2 = a22 - qm;
    const float off2 = a01*a01 + a02*a02 + a12*a12;
    float p2 = (d0*d0 + d1*d1 + d2*d2) * (1.0f / 6.0f) + off2 * (1.0f / 3.0f);
    p2 = fmaxf(p2, 1.0e-24f);
    const float detB = d0 * (d1*d2 - a12*a12)
                     - a01 * (a01*d2 - a12*a02)
                     + a02 * (a01*a12 - d1*a02);
    const float ip  = rsqrtf(p2);            // 1/p
    float r = 0.5f * detB * (ip * ip * ip);
    r = fminf(fmaxf(r, -1.0f), 1.0f);
    const float phi = acosf(r) * (1.0f / 3.0f);
    const float twop = 2.0f * p2 * ip;       // 2p
    const float l1 = qm + twop * __cosf(phi);                 // largest
    const float l3 = qm + twop * __cosf(phi + 2.0943951f);    // smallest
    const float l2 = 3.0f * qm - l1 - l3;

    // cancellation-free divided differences of f(x)=1/sqrt(x)
    const float u = sqrtf(l1), v = sqrtf(l2), w = sqrtf(l3);
    const float uv = u + v, vw = v + w, uw = u + w;
    const float rden = 1.0f / ((u * v * w) * uv * vw * uw);
    const float c2 = (u + v + w) * rden;
    const float c1 = -(w * vw * uw) * rden;
    const float c0 = (v * w) * (vw * uv * uw) * rden;   // = 1/u

    // S = c0*I + c1*(A-l1 I) + c2*(A-l1 I)(A-l2 I)
    const float e0 = a00 - l1, e1 = a11 - l1, e2 = a22 - l1;
    const float g0 = a00 - l2, g1 = a11 - l2, g2 = a22 - l2;
    const float P00 = e0*g0 + a01*a01 + a02*a02;
    const float P01 = a01*(e0 + g1) + a02*a12;
    const float P02 = a02*(e0 + g2) + a01*a12;
    const float P11 = a01*a01 + e1*g1 + a12*a12;
    const float P12 = a12*(e1 + g2) + a01*a02;
    const float P22 = a02*a02 + a12*a12 + e2*g2;

    const float S00 = fmaf(c2, P00, fmaf(c1, e0, c0));
    const float S01 = fmaf(c2, P01, c1 * a01);
    const float S02 = fmaf(c2, P02, c1 * a02);
    const float S11 = fmaf(c2, P11, fmaf(c1, e1, c0));
    const float S12 = fmaf(c2, P12, c1 * a12);
    const float S22 = fmaf(c2, P22, fmaf(c1, e2, c0));

    // bias b = -S*m folds the mean subtraction into the transform
    const float bb0 = -(S00*m0 + S01*m1 + S02*m2);
    const float bb1 = -(S01*m0 + S11*m1 + S12*m2);
    const float bb2 = -(S02*m0 + S12*m1 + S22*m2);

    // ---- epilogue: transform from registers + weight, streaming stores ----
    if (valid) {
        const float4* __restrict__ w4p = (const float4*)weight;
        float4* __restrict__ xout = (float4*)(out + sample * 768);

        #pragma unroll
        for (int c = 0; c < 2; c++) {
            float4 a = x[c], b = x[2 + c], d = x[4 + c];
            float4 wv = __ldg(&w4p[c * 32 + lane]);

            float4 o;
            o.x = fmaf(S00, a.x, fmaf(S01, b.x, fmaf(S02, d.x, bb0))) * wv.x;
            o.y = fmaf(S00, a.y, fmaf(S01, b.y, fmaf(S02, d.y, bb0))) * wv.y;
            o.z = fmaf(S00, a.z, fmaf(S01, b.z, fmaf(S02, d.z, bb0))) * wv.z;
            o.w = fmaf(S00, a.w, fmaf(S01, b.w, fmaf(S02, d.w, bb0))) * wv.w;
            __stcs(&xout[       c * 32 + lane], o);

            o.x = fmaf(S01, a.x, fmaf(S11, b.x, fmaf(S12, d.x, bb1))) * wv.x;
            o.y = fmaf(S01, a.y, fmaf(S11, b.y, fmaf(S12, d.y, bb1))) * wv.y;
            o.z = fmaf(S01, a.z, fmaf(S11, b.z, fmaf(S12, d.z, bb1))) * wv.z;
            o.w = fmaf(S01, a.w, fmaf(S11, b.w, fmaf(S12, d.w, bb1))) * wv.w;
            __stcs(&xout[ 64 +  c * 32 + lane], o);

            o.x = fmaf(S02, a.x, fmaf(S12, b.x, fmaf(S22, d.x, bb2))) * wv.x;
            o.y = fmaf(S02, a.y, fmaf(S12, b.y, fmaf(S22, d.y, bb2))) * wv.y;
            o.z = fmaf(S02, a.z, fmaf(S12, b.z, fmaf(S22, d.z, bb2))) * wv.z;
            o.w = fmaf(S02, a.w, fmaf(S12, b.w, fmaf(S22, d.w, bb2))) * wv.w;
            __stcs(&xout[128 +  c * 32 + lane], o);
        }
    }
}

extern "C" void kernel_launch(void* const* d_in, const int* in_sizes, int n_in,
                              void* d_out, int out_size)
{
    const float* in = (const float*)d_in[0];
    const float* w  = (const float*)d_in[1];
    float* out      = (float*)d_out;

    int nSamples = in_sizes[0] / 768;        // N*3*256 elements -> N samples
    eqln_kernel<<<nSamples, 32>>>(in, w, out, nSamples);
}

// round 16
// speedup vs baseline: 1.0050x; 1.0005x over previous
#include <cuda_runtime.h>
#include <cstdint>

// EquivariantLayerNorm: out = (covar + EPS*I)^{-1/2} @ (x - mean) * weight
// covar = xc @ xc^T / D + EPS*diag(1,2,3),  x: (N, 3, 256) fp32.
//
// FINAL (== R13 champion, 63.0 us, rel_err 1.1e-7):
//   - One WARP per sample; each lane holds 6 float4 in registers (__ldcs,
//     evict-first) -> no smem round-trip, MLP=6 front-batched LDG.128.
//   - 5-level xor-butterfly leaves all 9 covariance sums in every lane.
//   - A^{-1/2} in closed form: trigonometric eigenvalues + Newton-form
//     quadratic with cancellation-free divided differences of 1/sqrt
//     (exact for 3x3 SPD; stable for coincident eigenvalues). Identity
//     used: V diag(1/sqrt(s+eps)) V^T over SVD(covar) == (covar+eps I)^{-1/2}.
//   - bias b = -S*m folds mean subtraction into the transform.
//   - Fused epilogue from registers, streaming stores (__stcs).
//   - Barrier-free; 64-thread blocks (2 samples), 64 regs, zero smem.
//
// Measured roofline position: DRAM 77% (6.1 TB/s) with issue/fma/occ all
// far from saturation across R12-R15 variants -> binding limit is the
// mixed 1:1 read/write HBM3e stream; traffic is at the 384 MiB minimum.

__device__ __forceinline__ float sum4(float4 a) {
    return (a.x + a.y) + (a.z + a.w);
}
__device__ __forceinline__ float dot4(float4 a, float4 b, float acc) {
    acc = fmaf(a.x, b.x, acc);
    acc = fmaf(a.y, b.y, acc);
    acc = fmaf(a.z, b.z, acc);
    acc = fmaf(a.w, b.w, acc);
    return acc;
}

__global__ void __launch_bounds__(64, 16) eqln_kernel(
    const float* __restrict__ in,
    const float* __restrict__ weight,
    float* __restrict__ out,
    int nSamples)
{
    const int warp = threadIdx.x >> 5;   // 0..1
    const int lane = threadIdx.x & 31;

    long sample = (long)blockIdx.x * 2 + warp;
    const bool valid = (sample < (long)nSamples);
    long ls = valid ? sample : (long)nSamples - 1;   // clamp for safe load

    // ---- front-batched register loads: 6 independent LDG.128 per lane ----
    const float4* __restrict__ xin = (const float4*)(in + ls * 768);
    float4 x[6];
    x[0] = __ldcs(&xin[       lane]);
    x[1] = __ldcs(&xin[ 32 +  lane]);
    x[2] = __ldcs(&xin[ 64 +  lane]);
    x[3] = __ldcs(&xin[ 96 +  lane]);
    x[4] = __ldcs(&xin[128 +  lane]);
    x[5] = __ldcs(&xin[160 +  lane]);

    // ---- 9-quantity reduction (row sums + raw second moments) ----
    float s[9];
    s[0] = sum4(x[0]) + sum4(x[1]);
    s[1] = sum4(x[2]) + sum4(x[3]);
    s[2] = sum4(x[4]) + sum4(x[5]);
    s[3] = dot4(x[1], x[1], dot4(x[0], x[0], 0.0f));
    s[4] = dot4(x[1], x[3], dot4(x[0], x[2], 0.0f));
    s[5] = dot4(x[1], x[5], dot4(x[0], x[4], 0.0f));
    s[6] = dot4(x[3], x[3], dot4(x[2], x[2], 0.0f));
    s[7] = dot4(x[3], x[5], dot4(x[2], x[4], 0.0f));
    s[8] = dot4(x[5], x[5], dot4(x[4], x[4], 0.0f));

    // 5-level butterfly: every lane ends with the full sums
    #pragma unroll
    for (int q = 0; q < 9; q++) {
        #pragma unroll
        for (int o = 16; o > 0; o >>= 1)
            s[q] += __shfl_xor_sync(0xffffffffu, s[q], o);
    }

    // ---- closed-form A^{-1/2} (redundant across the 32 lanes) ----
    const float invD = 1.0f / 256.0f;
    const float m0 = s[0] * invD, m1 = s[1] * invD, m2 = s[2] * invD;

    // A = covar + EPS*diag(1,2,3) + EPS*I   (the +EPS*I from 1/sqrt(s+eps))
    const float a00 = fmaf(s[3], invD, -m0 * m0) + 2.0e-3f;
    const float a01 = fmaf(s[4], invD, -m0 * m1);
    const float a02 = fmaf(s[5], invD, -m0 * m2);
    const float a11 = fmaf(s[6], invD, -m1 * m1) + 3.0e-3f;
    const float a12 = fmaf(s[7], invD, -m1 * m2);
    const float a22 = fmaf(s[8], invD, -m2 * m2) + 4.0e-3f;

    // eigenvalues (trigonometric method); A >= 2e-3 I so all roots positive
    const float qm  = (a00 + a11 + a22) * (1.0f / 3.0f);
    const float d0 = a00 - qm, d1 = a11 - qm, d2 = a22 - qm;
    const float off2 = a01*a01 + a02*a02 + a12*a12;
    float p2 = (d0*d0 + d1*d1 + d2*d2) * (1.0f / 6.0f) + off2 * (1.0f / 3.0f);
    p2 = fmaxf(p2, 1.0e-24f);
    const float detB = d0 * (d1*d2 - a12*a12)
                     - a01 * (a01*d2 - a12*a02)
                     + a02 * (a01*a12 - d1*a02);
    const float ip  = rsqrtf(p2);            // 1/p
    float r = 0.5f * detB * (ip * ip * ip);
    r = fminf(fmaxf(r, -1.0f), 1.0f);
    const float phi = acosf(r) * (1.0f / 3.0f);
    const float twop = 2.0f * p2 * ip;       // 2p
    const float l1 = qm + twop * __cosf(phi);                 // largest
    const float l3 = qm + twop * __cosf(phi + 2.0943951f);    // smallest
    const float l2 = 3.0f * qm - l1 - l3;

    // cancellation-free divided differences of f(x)=1/sqrt(x)
    const float u = sqrtf(l1), v = sqrtf(l2), w = sqrtf(l3);
    const float uv = u + v, vw = v + w, uw = u + w;
    const float rden = 1.0f / ((u * v * w) * uv * vw * uw);
    const float c2 = (u + v + w) * rden;
    const float c1 = -(w * vw * uw) * rden;
    const float c0 = (v * w) * (vw * uv * uw) * rden;   // = 1/u

    // S = c0*I + c1*(A-l1 I) + c2*(A-l1 I)(A-l2 I)
    const float e0 = a00 - l1, e1 = a11 - l1, e2 = a22 - l1;
    const float g0 = a00 - l2, g1 = a11 - l2, g2 = a22 - l2;
    const float P00 = e0*g0 + a01*a01 + a02*a02;
    const float P01 = a01*(e0 + g1) + a02*a12;
    const float P02 = a02*(e0 + g2) + a01*a12;
    const float P11 = a01*a01 + e1*g1 + a12*a12;
    const float P12 = a12*(e1 + g2) + a01*a02;
    const float P22 = a02*a02 + a12*a12 + e2*g2;

    const float S00 = fmaf(c2, P00, fmaf(c1, e0, c0));
    const float S01 = fmaf(c2, P01, c1 * a01);
    const float S02 = fmaf(c2, P02, c1 * a02);
    const float S11 = fmaf(c2, P11, fmaf(c1, e1, c0));
    const float S12 = fmaf(c2, P12, c1 * a12);
    const float S22 = fmaf(c2, P22, fmaf(c1, e2, c0));

    // bias b = -S*m folds the mean subtraction into the transform
    const float bb0 = -(S00*m0 + S01*m1 + S02*m2);
    const float bb1 = -(S01*m0 + S11*m1 + S12*m2);
    const float bb2 = -(S02*m0 + S12*m1 + S22*m2);

    // ---- epilogue: transform from registers + weight, streaming stores ----
    if (valid) {
        const float4* __restrict__ w4p = (const float4*)weight;
        float4* __restrict__ xout = (float4*)(out + sample * 768);

        #pragma unroll
        for (int c = 0; c < 2; c++) {
            float4 a = x[c], b = x[2 + c], d = x[4 + c];
            float4 wv = __ldg(&w4p[c * 32 + lane]);

            float4 o;
            o.x = fmaf(S00, a.x, fmaf(S01, b.x, fmaf(S02, d.x, bb0))) * wv.x;
            o.y = fmaf(S00, a.y, fmaf(S01, b.y, fmaf(S02, d.y, bb0))) * wv.y;
            o.z = fmaf(S00, a.z, fmaf(S01, b.z, fmaf(S02, d.z, bb0))) * wv.z;
            o.w = fmaf(S00, a.w, fmaf(S01, b.w, fmaf(S02, d.w, bb0))) * wv.w;
            __stcs(&xout[       c * 32 + lane], o);

            o.x = fmaf(S01, a.x, fmaf(S11, b.x, fmaf(S12, d.x, bb1))) * wv.x;
            o.y = fmaf(S01, a.y, fmaf(S11, b.y, fmaf(S12, d.y, bb1))) * wv.y;
            o.z = fmaf(S01, a.z, fmaf(S11, b.z, fmaf(S12, d.z, bb1))) * wv.z;
            o.w = fmaf(S01, a.w, fmaf(S11, b.w, fmaf(S12, d.w, bb1))) * wv.w;
            __stcs(&xout[ 64 +  c * 32 + lane], o);

            o.x = fmaf(S02, a.x, fmaf(S12, b.x, fmaf(S22, d.x, bb2))) * wv.x;
            o.y = fmaf(S02, a.y, fmaf(S12, b.y, fmaf(S22, d.y, bb2))) * wv.y;
            o.z = fmaf(S02, a.z, fmaf(S12, b.z, fmaf(S22, d.z, bb2))) * wv.z;
            o.w = fmaf(S02, a.w, fmaf(S12, b.w, fmaf(S22, d.w, bb2))) * wv.w;
            __stcs(&xout[128 +  c * 32 + lane], o);
        }
    }
}

extern "C" void kernel_launch(void* const* d_in, const int* in_sizes, int n_in,
                              void* d_out, int out_size)
{
    const float* in = (const float*)d_in[0];
    const float* w  = (const float*)d_in[1];
    float* out      = (float*)d_out;

    int nSamples = in_sizes[0] / 768;        // N*3*256 elements -> N samples
    int grid = (nSamples + 1) / 2;           // 2 samples per 64-thread block
    eqln_kernel<<<grid, 64>>>(in, w, out, nSamples);
}